// round 5
// baseline (speedup 1.0000x reference)
#include <cuda_runtime.h>
#include <cstdint>
#include <cstddef>

#define K_DIM 1024
#define N_DIM 1024

// Quantized operands stored as fp32 (NOT bf16-exact anymore: scales are inexact)
__device__ __align__(16) float g_xq[(size_t)8 * 8192 * 1024];
__device__ __align__(16) float g_wq[(size_t)1024 * 1024];

// ln(2) rounded to fp32 — the constant XLA bakes in for log2/exp2 compositions.
#define LN2F 0.69314718246459960938f

// jnp.log2(x)  ==  lax.log(x) / lax.log(2)   (fp32 div, libdevice logf)
__device__ __forceinline__ float jax_log2(float x) {
    return logf(x) / LN2F;
}
// jnp.exp2(v)  ==  exp(v * log(2))           (fp32 mul, libdevice expf)
__device__ __forceinline__ float jax_exp2(float v) {
    return expf(v * LN2F);
}

// Literal _fp8_e5m2_round from the reference, with JAX's transcendental lowerings.
__device__ __forceinline__ float e5m2_jax(float v) {
    float av = fabsf(v);
    if (!(av > 0.f)) return 0.f;
    float sat = fminf(av, 57344.f);
    float e = fmaxf(floorf(jax_log2(sat)), -14.f);
    float step = jax_exp2(e - 2.f);          // NOT an exact pow2 in general
    float q = rintf(sat / step) * step;      // true fp32 division, RNE round
    return copysignf(q, v);
}

// Literal block scale: exp2(floor(log2(amax)) - 15), JAX lowering.
__device__ __forceinline__ float jax_block_scale(float amax) {
    if (amax > 0.f)
        return jax_exp2(floorf(jax_log2(amax)) - 15.f);
    return 1.f;
}

// One thread = one 32-element MX block along the last dim.
__global__ void quant_blocks(const float* __restrict__ x,
                             float* __restrict__ q, int nblk) {
    int b = blockIdx.x * blockDim.x + threadIdx.x;
    if (b >= nblk) return;
    const float4* p = reinterpret_cast<const float4*>(x) + (size_t)b * 8;
    float4 v[8];
    float amax = 0.f;
#pragma unroll
    for (int i = 0; i < 8; i++) {
        v[i] = p[i];
        amax = fmaxf(amax, fmaxf(fmaxf(fabsf(v[i].x), fabsf(v[i].y)),
                                 fmaxf(fabsf(v[i].z), fabsf(v[i].w))));
    }
    float scale = jax_block_scale(amax);
    const float* f = reinterpret_cast<const float*>(v);
    float4 ov[8];
    float* o = reinterpret_cast<float*>(ov);
#pragma unroll
    for (int i = 0; i < 32; i++)
        o[i] = e5m2_jax(f[i] / scale) * scale;   // true division by inexact scale
    float4* dst = reinterpret_cast<float4*>(q) + (size_t)b * 8;
#pragma unroll
    for (int i = 0; i < 8; i++) dst[i] = ov[i];
}

// ---------------- exact-fp32 SGEMM (FFMA2) with fused literal output quant ----
#define TBM 128
#define TBN 128
#define TBK 16

__device__ __forceinline__ unsigned long long pack2(float lo, float hi) {
    unsigned long long r;
    asm("mov.b64 %0, {%1, %2};" : "=l"(r) : "f"(lo), "f"(hi));
    return r;
}
__device__ __forceinline__ void ffma2(unsigned long long& acc,
                                      unsigned long long a,
                                      unsigned long long b) {
    asm("fma.rn.f32x2 %0, %1, %2, %0;" : "+l"(acc) : "l"(a), "l"(b));
}
__device__ __forceinline__ float2 unpack2(unsigned long long v) {
    float2 r;
    asm("mov.b64 {%0, %1}, %2;" : "=f"(r.x), "=f"(r.y) : "l"(v));
    return r;
}

__global__ __launch_bounds__(256) void gemm_fp32_qd(const float* __restrict__ bias,
                                                    float* __restrict__ out) {
    __shared__ float sA[TBK][TBM];
    __shared__ float sB[TBK][TBN];
    __shared__ float sBias[TBN];

    const int tid = threadIdx.x;
    const int m0 = blockIdx.y * TBM;
    const int n0 = blockIdx.x * TBN;
    if (tid < TBN) sBias[tid] = bias[n0 + tid];

    const int ty = tid >> 4;    // 0..15 : m micro-tile (8 rows)
    const int tn = tid & 15;    // 0..15 : n micro-tile (8 cols)

    const int lrow = tid >> 1;          // 0..127
    const int lk = (tid & 1) * 8;       // 0 or 8

    unsigned long long acc2[8][4];
#pragma unroll
    for (int i = 0; i < 8; i++)
#pragma unroll
        for (int j = 0; j < 4; j++) acc2[i][j] = pack2(0.f, 0.f);

    const float* gA = &g_xq[(size_t)(m0 + lrow) * K_DIM + lk];
    const float* gB = &g_wq[(size_t)(n0 + lrow) * K_DIM + lk];

    for (int kt = 0; kt < K_DIM / TBK; kt++) {
        float4 a0 = *reinterpret_cast<const float4*>(gA + kt * TBK);
        float4 a1 = *reinterpret_cast<const float4*>(gA + kt * TBK + 4);
        float4 b0 = *reinterpret_cast<const float4*>(gB + kt * TBK);
        float4 b1 = *reinterpret_cast<const float4*>(gB + kt * TBK + 4);
        __syncthreads();
        sA[lk + 0][lrow] = a0.x; sA[lk + 1][lrow] = a0.y;
        sA[lk + 2][lrow] = a0.z; sA[lk + 3][lrow] = a0.w;
        sA[lk + 4][lrow] = a1.x; sA[lk + 5][lrow] = a1.y;
        sA[lk + 6][lrow] = a1.z; sA[lk + 7][lrow] = a1.w;
        sB[lk + 0][lrow] = b0.x; sB[lk + 1][lrow] = b0.y;
        sB[lk + 2][lrow] = b0.z; sB[lk + 3][lrow] = b0.w;
        sB[lk + 4][lrow] = b1.x; sB[lk + 5][lrow] = b1.y;
        sB[lk + 6][lrow] = b1.z; sB[lk + 7][lrow] = b1.w;
        __syncthreads();

#pragma unroll
        for (int k = 0; k < TBK; k++) {
            float4 A0 = *reinterpret_cast<const float4*>(&sA[k][ty * 8]);
            float4 A1 = *reinterpret_cast<const float4*>(&sA[k][ty * 8 + 4]);
            float4 B0 = *reinterpret_cast<const float4*>(&sB[k][tn * 8]);
            float4 B1 = *reinterpret_cast<const float4*>(&sB[k][tn * 8 + 4]);
            unsigned long long bp[4];
            bp[0] = pack2(B0.x, B0.y);
            bp[1] = pack2(B0.z, B0.w);
            bp[2] = pack2(B1.x, B1.y);
            bp[3] = pack2(B1.z, B1.w);
            const float av[8] = {A0.x, A0.y, A0.z, A0.w, A1.x, A1.y, A1.z, A1.w};
#pragma unroll
            for (int i = 0; i < 8; i++) {
                unsigned long long a2 = pack2(av[i], av[i]);
#pragma unroll
                for (int j = 0; j < 4; j++) ffma2(acc2[i][j], a2, bp[j]);
            }
        }
    }

    // Epilogue: +bias, literal MX e5m2 quant-dequant over 32-n blocks.
    // One block = 4 adjacent tn (lane bits 0,1), same ty.
#pragma unroll
    for (int r = 0; r < 8; r++) {
        float v[8];
        float amax = 0.f;
#pragma unroll
        for (int j = 0; j < 4; j++) {
            float2 p = unpack2(acc2[r][j]);
            v[j * 2 + 0] = p.x + sBias[tn * 8 + j * 2 + 0];
            v[j * 2 + 1] = p.y + sBias[tn * 8 + j * 2 + 1];
            amax = fmaxf(amax, fmaxf(fabsf(v[j * 2]), fabsf(v[j * 2 + 1])));
        }
        amax = fmaxf(amax, __shfl_xor_sync(0xffffffffu, amax, 1));
        amax = fmaxf(amax, __shfl_xor_sync(0xffffffffu, amax, 2));
        float scale = jax_block_scale(amax);
        float4 o0, o1;
        o0.x = e5m2_jax(v[0] / scale) * scale;
        o0.y = e5m2_jax(v[1] / scale) * scale;
        o0.z = e5m2_jax(v[2] / scale) * scale;
        o0.w = e5m2_jax(v[3] / scale) * scale;
        o1.x = e5m2_jax(v[4] / scale) * scale;
        o1.y = e5m2_jax(v[5] / scale) * scale;
        o1.z = e5m2_jax(v[6] / scale) * scale;
        o1.w = e5m2_jax(v[7] / scale) * scale;
        float* orow = out + (size_t)(m0 + ty * 8 + r) * N_DIM + n0 + tn * 8;
        *reinterpret_cast<float4*>(orow) = o0;
        *reinterpret_cast<float4*>(orow + 4) = o1;
    }
}

extern "C" void kernel_launch(void* const* d_in, const int* in_sizes, int n_in,
                              void* d_out, int out_size) {
    const float* x = (const float*)d_in[0];
    const float* w = (const float*)d_in[1];
    const float* bias = (const float*)d_in[2];
    float* out = (float*)d_out;

    int Mtot = in_sizes[0] / K_DIM;   // 65536
    int nbx = in_sizes[0] / 32;
    int nbw = in_sizes[1] / 32;

    void* pxq = nullptr;
    void* pwq = nullptr;
    cudaGetSymbolAddress(&pxq, g_xq);
    cudaGetSymbolAddress(&pwq, g_wq);

    quant_blocks<<<(nbx + 255) / 256, 256>>>(x, (float*)pxq, nbx);
    quant_blocks<<<(nbw + 255) / 256, 256>>>(w, (float*)pwq, nbw);

    dim3 grid(N_DIM / TBN, Mtot / TBM);
    gemm_fp32_qd<<<grid, 256>>>(bias, out);
}

// round 7
// speedup vs baseline: 2.2915x; 2.2915x over previous
#include <cuda_runtime.h>
#include <cuda_bf16.h>
#include <cstdint>
#include <cstddef>

#define K_DIM 1024
#define N_DIM 1024
#define NKB 32
#define LN2F 0.69314718246459960938f

#define BM 128
#define BN 128
#define BK 32
#define SSTRIDE 40

// Exact e5m2 grid values (bf16-exact) + per-32-block scales (fp32, inexact jax)
__device__ __align__(16) __nv_bfloat16 g_xv[(size_t)8 * 8192 * 1024];
__device__ __align__(16) __nv_bfloat16 g_wv[(size_t)1024 * 1024];
__device__ __align__(16) float g_xs[(size_t)NKB * 65536];   // [kb][row]
__device__ __align__(16) float g_ws[(size_t)NKB * 1024];    // [kb][row]

// floor(logf(s)/ln2f) with exponent-bits fast path (bitwise-equal in fast region)
__device__ __forceinline__ int jax_floor_log2(float s) {
    uint32_t b = __float_as_uint(s);
    uint32_t mant = b & 0x7fffffu;
    int ef = (int)(b >> 23);
    if (ef == 0 || mant >= 0x7ff000u || (mant != 0u && mant <= 0x4000u))
        return (int)floorf(logf(s) / LN2F);
    return ef - 127;
}

// Literal jax block scale: expf((floor(log2(amax)) - 15) * ln2f)
__device__ __forceinline__ float jax_scale(float amax) {
    if (!(amax > 0.f)) return 1.f;
    int E = jax_floor_log2(amax);
    return expf((float)(E - 15) * LN2F);
}

// One thread = one 32-element MX block. Emits exact grid values (bf16) + scale.
__global__ void quant_v(const float* __restrict__ x, __nv_bfloat16* __restrict__ qv,
                        float* __restrict__ qs, int nblk, int rows) {
    __shared__ float sStep[30];
    if (threadIdx.x < 30) sStep[threadIdx.x] = expf((float)((int)threadIdx.x - 16) * LN2F);
    __syncthreads();
    int b = blockIdx.x * blockDim.x + threadIdx.x;
    if (b >= nblk) return;
    const float4* p = reinterpret_cast<const float4*>(x) + (size_t)b * 8;
    float4 v[8];
    float amax = 0.f;
#pragma unroll
    for (int i = 0; i < 8; i++) {
        v[i] = p[i];
        amax = fmaxf(amax, fmaxf(fmaxf(fabsf(v[i].x), fabsf(v[i].y)),
                                 fmaxf(fabsf(v[i].z), fabsf(v[i].w))));
    }
    float scale = jax_scale(amax);
    const float* f = reinterpret_cast<const float*>(v);
    uint4 ov[4];                                   // 32 bf16 = 64 bytes = 4 x uint4
    unsigned short* o = reinterpret_cast<unsigned short*>(ov);
#pragma unroll
    for (int i = 0; i < 32; i++) {
        float t = f[i] / scale;            // true div: int selection bitwise as ref
        float av = fabsf(t);
        float r = 0.f;
        if (av > 0.f) {
            float sat = fminf(av, 57344.f);
            int e = jax_floor_log2(sat);
            e = e < -14 ? -14 : e;
            float step = sStep[e + 14];    // bitwise == expf((e-2)*ln2f)
            float n = rintf(sat / step);   // true div: bitwise as ref
            r = copysignf(ldexpf(n, e - 2), t);   // EXACT e5m2 grid value
        }
        o[i] = __bfloat16_as_ushort(__float2bfloat16(r));  // exact
    }
    uint4* dst = reinterpret_cast<uint4*>(qv) + (size_t)b * 4;
#pragma unroll
    for (int i = 0; i < 4; i++) dst[i] = ov[i];
    qs[(size_t)(b & 31) * rows + (b >> 5)] = scale;
}

__device__ __forceinline__ void cp_async16(uint32_t dst, const void* src) {
    asm volatile("cp.async.cg.shared.global [%0], [%1], 16;\n" :: "r"(dst), "l"(src));
}

// 128x128 tile GEMM: exact bf16 HMMA on grid values per 32-k block, then fold
// chunk * (s_x * s_w) into fp32 master. Literal jax out-quant in epilogue.
__global__ __launch_bounds__(256) void gemm_qd(const float* __restrict__ bias,
                                               float* __restrict__ out, int mrows) {
    __shared__ __nv_bfloat16 sA[2][BM * SSTRIDE];
    __shared__ __nv_bfloat16 sB[2][BN * SSTRIDE];
    __shared__ float sSX[2][BM];
    __shared__ float sSW[2][BN];
    __shared__ float sBias[BN];
    __shared__ float sStep[30];

    const int tid = threadIdx.x;
    const int m0 = blockIdx.y * BM;
    const int n0 = blockIdx.x * BN;
    if (tid < 30) sStep[tid] = expf((float)(tid - 16) * LN2F);
    if (tid < BN) sBias[tid] = bias[n0 + tid];

    const int lane = tid & 31;
    const int warp = tid >> 5;
    const int wm = warp >> 2;
    const int wn = warp & 3;

    uint32_t sAu[2], sBu[2], sSXu[2], sSWu[2];
    sAu[0] = (uint32_t)__cvta_generic_to_shared(&sA[0][0]);
    sAu[1] = (uint32_t)__cvta_generic_to_shared(&sA[1][0]);
    sBu[0] = (uint32_t)__cvta_generic_to_shared(&sB[0][0]);
    sBu[1] = (uint32_t)__cvta_generic_to_shared(&sB[1][0]);
    sSXu[0] = (uint32_t)__cvta_generic_to_shared(&sSX[0][0]);
    sSXu[1] = (uint32_t)__cvta_generic_to_shared(&sSX[1][0]);
    sSWu[0] = (uint32_t)__cvta_generic_to_shared(&sSW[0][0]);
    sSWu[1] = (uint32_t)__cvta_generic_to_shared(&sSW[1][0]);

    float acc[4][4][4];
#pragma unroll
    for (int i = 0; i < 4; i++)
#pragma unroll
        for (int j = 0; j < 4; j++)
#pragma unroll
            for (int r = 0; r < 4; r++) acc[i][j][r] = 0.f;

    auto load_stage = [&](int stage, int kt) {
        int k0 = kt * BK;
#pragma unroll
        for (int t = 0; t < 2; t++) {
            int o = tid + t * 256;
            int row = o >> 2, ch = o & 3;
            const __nv_bfloat16* gsa = &g_xv[(size_t)(m0 + row) * K_DIM + k0 + ch * 8];
            cp_async16(sAu[stage] + (uint32_t)(row * SSTRIDE + ch * 8) * 2, gsa);
            const __nv_bfloat16* gsb = &g_wv[(size_t)(n0 + row) * K_DIM + k0 + ch * 8];
            cp_async16(sBu[stage] + (uint32_t)(row * SSTRIDE + ch * 8) * 2, gsb);
        }
        if (tid < 32)
            cp_async16(sSXu[stage] + tid * 16, &g_xs[(size_t)kt * mrows + m0 + tid * 4]);
        else if (tid < 64)
            cp_async16(sSWu[stage] + (tid - 32) * 16,
                       &g_ws[(size_t)kt * N_DIM + n0 + (tid - 32) * 4]);
        asm volatile("cp.async.commit_group;\n");
    };

    const int gid = lane >> 2, tig = lane & 3;
    const int NK = K_DIM / BK;
    load_stage(0, 0);

    for (int kt = 0; kt < NK; kt++) {
        if (kt + 1 < NK) {
            load_stage((kt + 1) & 1, kt + 1);
            asm volatile("cp.async.wait_group 1;\n");
        } else {
            asm volatile("cp.async.wait_group 0;\n");
        }
        __syncthreads();
        const int st = kt & 1;

        uint32_t a[2][4][4], b[2][4][2];
#pragma unroll
        for (int kk = 0; kk < 2; kk++) {
#pragma unroll
            for (int mf = 0; mf < 4; mf++) {
                uint32_t addr = sAu[st] +
                    (uint32_t)(((wm * 64 + mf * 16 + (lane & 15)) * SSTRIDE) +
                               kk * 16 + (lane >> 4) * 8) * 2;
                asm volatile("ldmatrix.sync.aligned.m8n8.x4.shared.b16 {%0,%1,%2,%3}, [%4];\n"
                             : "=r"(a[kk][mf][0]), "=r"(a[kk][mf][1]),
                               "=r"(a[kk][mf][2]), "=r"(a[kk][mf][3])
                             : "r"(addr));
            }
#pragma unroll
            for (int nf = 0; nf < 4; nf++) {
                uint32_t addr = sBu[st] +
                    (uint32_t)(((wn * 32 + nf * 8 + (lane & 7)) * SSTRIDE) +
                               kk * 16 + ((lane >> 3) & 1) * 8) * 2;
                asm volatile("ldmatrix.sync.aligned.m8n8.x2.shared.b16 {%0,%1}, [%2];\n"
                             : "=r"(b[kk][nf][0]), "=r"(b[kk][nf][1]) : "r"(addr));
            }
        }

        float sxv[4][2], swv[4][2];
#pragma unroll
        for (int mf = 0; mf < 4; mf++) {
            sxv[mf][0] = sSX[st][wm * 64 + mf * 16 + gid];
            sxv[mf][1] = sSX[st][wm * 64 + mf * 16 + 8 + gid];
        }
#pragma unroll
        for (int nf = 0; nf < 4; nf++) {
            swv[nf][0] = sSW[st][wn * 32 + nf * 8 + tig * 2];
            swv[nf][1] = sSW[st][wn * 32 + nf * 8 + tig * 2 + 1];
        }

#pragma unroll
        for (int mf = 0; mf < 4; mf++)
#pragma unroll
            for (int nf = 0; nf < 4; nf++) {
                float c0 = 0.f, c1 = 0.f, c2 = 0.f, c3 = 0.f;
#pragma unroll
                for (int kk = 0; kk < 2; kk++) {
                    asm volatile(
                        "mma.sync.aligned.m16n8k16.row.col.f32.bf16.bf16.f32 "
                        "{%0,%1,%2,%3}, {%4,%5,%6,%7}, {%8,%9}, {%0,%1,%2,%3};\n"
                        : "+f"(c0), "+f"(c1), "+f"(c2), "+f"(c3)
                        : "r"(a[kk][mf][0]), "r"(a[kk][mf][1]),
                          "r"(a[kk][mf][2]), "r"(a[kk][mf][3]),
                          "r"(b[kk][nf][0]), "r"(b[kk][nf][1]));
                }
                acc[mf][nf][0] = fmaf(c0, sxv[mf][0] * swv[nf][0], acc[mf][nf][0]);
                acc[mf][nf][1] = fmaf(c1, sxv[mf][0] * swv[nf][1], acc[mf][nf][1]);
                acc[mf][nf][2] = fmaf(c2, sxv[mf][1] * swv[nf][0], acc[mf][nf][2]);
                acc[mf][nf][3] = fmaf(c3, sxv[mf][1] * swv[nf][1], acc[mf][nf][3]);
            }
        __syncthreads();
    }

    // Epilogue: +bias, literal jax MX e5m2 quant-dequant over 32 consecutive n.
#pragma unroll
    for (int mf = 0; mf < 4; mf++) {
#pragma unroll
        for (int h = 0; h < 2; h++) {
            int rl = wm * 64 + mf * 16 + h * 8 + gid;
            float v[8];
            float amax = 0.f;
#pragma unroll
            for (int nf = 0; nf < 4; nf++)
#pragma unroll
                for (int j = 0; j < 2; j++) {
                    int cl = wn * 32 + nf * 8 + tig * 2 + j;
                    float val = acc[mf][nf][h * 2 + j] + sBias[cl];
                    v[nf * 2 + j] = val;
                    amax = fmaxf(amax, fabsf(val));
                }
            amax = fmaxf(amax, __shfl_xor_sync(0xffffffffu, amax, 1));
            amax = fmaxf(amax, __shfl_xor_sync(0xffffffffu, amax, 2));
            float scale = jax_scale(amax);
            float* orow = out + (size_t)(m0 + rl) * N_DIM + n0 + wn * 32;
#pragma unroll
            for (int nf = 0; nf < 4; nf++) {
                float2 qv;
#pragma unroll
                for (int j = 0; j < 2; j++) {
                    float t = v[nf * 2 + j] / scale;
                    float av = fabsf(t);
                    float r = 0.f;
                    if (av > 0.f) {
                        float sat = fminf(av, 57344.f);
                        int e = jax_floor_log2(sat);
                        e = e < -14 ? -14 : e;
                        float step = sStep[e + 14];
                        float q = rintf(sat / step) * step;   // literal ref math
                        r = copysignf(q, t) * scale;
                    }
                    (j == 0 ? qv.x : qv.y) = r;
                }
                *reinterpret_cast<float2*>(orow + nf * 8 + tig * 2) = qv;
            }
        }
    }
}

extern "C" void kernel_launch(void* const* d_in, const int* in_sizes, int n_in,
                              void* d_out, int out_size) {
    const float* x = (const float*)d_in[0];
    const float* w = (const float*)d_in[1];
    const float* bias = (const float*)d_in[2];
    float* out = (float*)d_out;

    int Mtot = in_sizes[0] / K_DIM;   // 65536
    int nbx = in_sizes[0] / 32;
    int nbw = in_sizes[1] / 32;

    void *pxv = nullptr, *pwv = nullptr, *pxs = nullptr, *pws = nullptr;
    cudaGetSymbolAddress(&pxv, g_xv);
    cudaGetSymbolAddress(&pwv, g_wv);
    cudaGetSymbolAddress(&pxs, g_xs);
    cudaGetSymbolAddress(&pws, g_ws);

    quant_v<<<(nbx + 255) / 256, 256>>>(x, (__nv_bfloat16*)pxv, (float*)pxs, nbx, Mtot);
    quant_v<<<(nbw + 255) / 256, 256>>>(w, (__nv_bfloat16*)pwv, (float*)pws, nbw, N_DIM);

    dim3 grid(N_DIM / BN, Mtot / BM);
    gemm_qd<<<grid, 256>>>(bias, out, Mtot);
}

// round 8
// speedup vs baseline: 2.6395x; 1.1518x over previous
#include <cuda_runtime.h>
#include <cuda_bf16.h>
#include <cstdint>
#include <cstddef>

#define K_DIM 1024
#define N_DIM 1024
#define NKB 32
#define LN2F 0.69314718246459960938f

#define BM 128
#define BN 128
#define BK 32
#define SSTRIDE 40
#define STG_ELEMS (BM * SSTRIDE)   // 5120 bf16 per stage per matrix

// Exact e5m2 grid values (bf16-exact) + per-32-block scales (fp32, inexact jax)
__device__ __align__(16) __nv_bfloat16 g_xv[(size_t)8 * 8192 * 1024];
__device__ __align__(16) __nv_bfloat16 g_wv[(size_t)1024 * 1024];
__device__ __align__(16) float g_xs[(size_t)NKB * 65536];   // [kb][row]
__device__ __align__(16) float g_ws[(size_t)NKB * 1024];    // [kb][row]

// floor(logf(s)/ln2f) with exponent-bits fast path (bitwise-equal in fast region)
__device__ __forceinline__ int jax_floor_log2(float s) {
    uint32_t b = __float_as_uint(s);
    uint32_t mant = b & 0x7fffffu;
    int ef = (int)(b >> 23);
    if (ef == 0 || mant >= 0x7ff000u || (mant != 0u && mant <= 0x4000u))
        return (int)floorf(logf(s) / LN2F);
    return ef - 127;
}

// Literal jax block scale: expf((floor(log2(amax)) - 15) * ln2f)
__device__ __forceinline__ float jax_scale(float amax) {
    if (!(amax > 0.f)) return 1.f;
    int E = jax_floor_log2(amax);
    return expf((float)(E - 15) * LN2F);
}

// One thread = one 32-element MX block. Emits exact grid values (bf16) + scale.
__global__ void quant_v(const float* __restrict__ x, __nv_bfloat16* __restrict__ qv,
                        float* __restrict__ qs, int nblk, int rows) {
    __shared__ float sStep[30];
    if (threadIdx.x < 30) sStep[threadIdx.x] = expf((float)((int)threadIdx.x - 16) * LN2F);
    __syncthreads();
    int b = blockIdx.x * blockDim.x + threadIdx.x;
    if (b >= nblk) return;
    const float4* p = reinterpret_cast<const float4*>(x) + (size_t)b * 8;
    float4 v[8];
    float amax = 0.f;
#pragma unroll
    for (int i = 0; i < 8; i++) {
        v[i] = p[i];
        amax = fmaxf(amax, fmaxf(fmaxf(fabsf(v[i].x), fabsf(v[i].y)),
                                 fmaxf(fabsf(v[i].z), fabsf(v[i].w))));
    }
    float scale = jax_scale(amax);
    const float* f = reinterpret_cast<const float*>(v);
    uint4 ov[4];                                   // 32 bf16 = 64 bytes
    unsigned short* o = reinterpret_cast<unsigned short*>(ov);
#pragma unroll
    for (int i = 0; i < 32; i++) {
        float t = f[i] / scale;            // true div: selection bitwise as ref
        float av = fabsf(t);
        float r = 0.f;
        if (av > 0.f) {
            float sat = fminf(av, 57344.f);
            int e = jax_floor_log2(sat);
            e = e < -14 ? -14 : e;
            float step = sStep[e + 14];    // bitwise == expf((e-2)*ln2f)
            float n = rintf(sat / step);   // true div: bitwise as ref
            r = copysignf(ldexpf(n, e - 2), t);   // EXACT e5m2 grid value
        }
        o[i] = __bfloat16_as_ushort(__float2bfloat16(r));  // exact
    }
    uint4* dst = reinterpret_cast<uint4*>(qv) + (size_t)b * 4;
#pragma unroll
    for (int i = 0; i < 4; i++) dst[i] = ov[i];
    qs[(size_t)(b & 31) * rows + (b >> 5)] = scale;
}

__device__ __forceinline__ void cp_async16(uint32_t dst, const void* src) {
    asm volatile("cp.async.cg.shared.global [%0], [%1], 16;\n" :: "r"(dst), "l"(src));
}

__device__ __forceinline__ unsigned long long pk2(float lo, float hi) {
    unsigned long long r;
    asm("mov.b64 %0, {%1, %2};" : "=l"(r) : "f"(lo), "f"(hi));
    return r;
}
__device__ __forceinline__ float2 upk2(unsigned long long v) {
    float2 r;
    asm("mov.b64 {%0, %1}, %2;" : "=f"(r.x), "=f"(r.y) : "l"(v));
    return r;
}
__device__ __forceinline__ unsigned long long mul2(unsigned long long a,
                                                   unsigned long long b) {
    unsigned long long r;
    asm("mul.rn.f32x2 %0, %1, %2;" : "=l"(r) : "l"(a), "l"(b));
    return r;
}
__device__ __forceinline__ void fma2(unsigned long long& acc, unsigned long long a,
                                     unsigned long long b) {
    asm("fma.rn.f32x2 %0, %1, %2, %0;" : "+l"(acc) : "l"(a), "l"(b));
}

// 128x128 tile GEMM, 16 warps (warp tile 32x32), 3-stage cp.async pipeline,
// exact bf16 HMMA per 32-k block + packed-f32x2 scale fold; literal jax out-quant.
__global__ __launch_bounds__(512) void gemm_qd(const float* __restrict__ bias,
                                               float* __restrict__ out, int mrows) {
    extern __shared__ __nv_bfloat16 dynsm[];
    __nv_bfloat16* sA = dynsm;                    // [3][STG_ELEMS]
    __nv_bfloat16* sB = dynsm + 3 * STG_ELEMS;    // [3][STG_ELEMS]
    __shared__ float sSX[3][BM];
    __shared__ float sSW[3][BN];
    __shared__ float sBias[BN];
    __shared__ float sStep[30];

    const int tid = threadIdx.x;
    const int m0 = blockIdx.y * BM;
    const int n0 = blockIdx.x * BN;
    if (tid < 30) sStep[tid] = expf((float)(tid - 16) * LN2F);
    if (tid < BN) sBias[tid] = bias[n0 + tid];

    const int lane = tid & 31;
    const int warp = tid >> 5;          // 0..15
    const int wm = warp >> 2;           // 0..3  (32 rows)
    const int wn = warp & 3;            // 0..3  (32 cols = one quant block)

    uint32_t sAu[3], sBu[3], sSXu[3], sSWu[3];
#pragma unroll
    for (int s = 0; s < 3; s++) {
        sAu[s] = (uint32_t)__cvta_generic_to_shared(sA + s * STG_ELEMS);
        sBu[s] = (uint32_t)__cvta_generic_to_shared(sB + s * STG_ELEMS);
        sSXu[s] = (uint32_t)__cvta_generic_to_shared(&sSX[s][0]);
        sSWu[s] = (uint32_t)__cvta_generic_to_shared(&sSW[s][0]);
    }

    unsigned long long acc2[2][4][2];
#pragma unroll
    for (int i = 0; i < 2; i++)
#pragma unroll
        for (int j = 0; j < 4; j++)
#pragma unroll
            for (int h = 0; h < 2; h++) acc2[i][j][h] = 0ull;

    const int grow = tid >> 2, gch = tid & 3;   // 512 threads: one 16B chunk of A and B
    auto load_stage = [&](int stage, int kt) {
        int k0 = kt * BK;
        cp_async16(sAu[stage] + (uint32_t)(grow * SSTRIDE + gch * 8) * 2,
                   &g_xv[(size_t)(m0 + grow) * K_DIM + k0 + gch * 8]);
        cp_async16(sBu[stage] + (uint32_t)(grow * SSTRIDE + gch * 8) * 2,
                   &g_wv[(size_t)(n0 + grow) * K_DIM + k0 + gch * 8]);
        if (tid < 32)
            cp_async16(sSXu[stage] + tid * 16, &g_xs[(size_t)kt * mrows + m0 + tid * 4]);
        else if (tid < 64)
            cp_async16(sSWu[stage] + (tid - 32) * 16,
                       &g_ws[(size_t)kt * N_DIM + n0 + (tid - 32) * 4]);
        asm volatile("cp.async.commit_group;\n");
    };

    const int gid = lane >> 2, tig = lane & 3;
    const int NK = K_DIM / BK;   // 32

    load_stage(0, 0);
    load_stage(1, 1);

    int st = 0;
    for (int kt = 0; kt < NK; kt++) {
        if (kt < NK - 1) {
            asm volatile("cp.async.wait_group 1;\n");
        } else {
            asm volatile("cp.async.wait_group 0;\n");
        }
        __syncthreads();
        if (kt + 2 < NK) {
            int pf = st + 2 >= 3 ? st - 1 : st + 2;
            load_stage(pf, kt + 2);
        }

        float c[2][4][4];
#pragma unroll
        for (int i = 0; i < 2; i++)
#pragma unroll
            for (int j = 0; j < 4; j++)
#pragma unroll
                for (int r = 0; r < 4; r++) c[i][j][r] = 0.f;

#pragma unroll
        for (int kk = 0; kk < 2; kk++) {
            uint32_t a[2][4], b[4][2];
#pragma unroll
            for (int mf = 0; mf < 2; mf++) {
                uint32_t addr = sAu[st] +
                    (uint32_t)(((wm * 32 + mf * 16 + (lane & 15)) * SSTRIDE) +
                               kk * 16 + (lane >> 4) * 8) * 2;
                asm volatile("ldmatrix.sync.aligned.m8n8.x4.shared.b16 {%0,%1,%2,%3}, [%4];\n"
                             : "=r"(a[mf][0]), "=r"(a[mf][1]),
                               "=r"(a[mf][2]), "=r"(a[mf][3])
                             : "r"(addr));
            }
#pragma unroll
            for (int nf = 0; nf < 4; nf++) {
                uint32_t addr = sBu[st] +
                    (uint32_t)(((wn * 32 + nf * 8 + (lane & 7)) * SSTRIDE) +
                               kk * 16 + ((lane >> 3) & 1) * 8) * 2;
                asm volatile("ldmatrix.sync.aligned.m8n8.x2.shared.b16 {%0,%1}, [%2];\n"
                             : "=r"(b[nf][0]), "=r"(b[nf][1]) : "r"(addr));
            }
#pragma unroll
            for (int mf = 0; mf < 2; mf++)
#pragma unroll
                for (int nf = 0; nf < 4; nf++) {
                    asm volatile(
                        "mma.sync.aligned.m16n8k16.row.col.f32.bf16.bf16.f32 "
                        "{%0,%1,%2,%3}, {%4,%5,%6,%7}, {%8,%9}, {%0,%1,%2,%3};\n"
                        : "+f"(c[mf][nf][0]), "+f"(c[mf][nf][1]),
                          "+f"(c[mf][nf][2]), "+f"(c[mf][nf][3])
                        : "r"(a[mf][0]), "r"(a[mf][1]), "r"(a[mf][2]), "r"(a[mf][3]),
                          "r"(b[nf][0]), "r"(b[nf][1]));
                }
        }

        // Packed scale fold: acc += c * (sx * sw), element-wise RN (bitwise ==
        // the scalar fmaf(c, sx*sw, acc) sequence).
        unsigned long long sxp[2][2], swp[4];
#pragma unroll
        for (int mf = 0; mf < 2; mf++) {
            float s0 = sSX[st][wm * 32 + mf * 16 + gid];
            float s1 = sSX[st][wm * 32 + mf * 16 + 8 + gid];
            sxp[mf][0] = pk2(s0, s0);
            sxp[mf][1] = pk2(s1, s1);
        }
#pragma unroll
        for (int nf = 0; nf < 4; nf++)
            swp[nf] = pk2(sSW[st][wn * 32 + nf * 8 + tig * 2],
                          sSW[st][wn * 32 + nf * 8 + tig * 2 + 1]);
#pragma unroll
        for (int mf = 0; mf < 2; mf++)
#pragma unroll
            for (int nf = 0; nf < 4; nf++) {
                fma2(acc2[mf][nf][0], pk2(c[mf][nf][0], c[mf][nf][1]),
                     mul2(sxp[mf][0], swp[nf]));
                fma2(acc2[mf][nf][1], pk2(c[mf][nf][2], c[mf][nf][3]),
                     mul2(sxp[mf][1], swp[nf]));
            }

        st = st + 1 >= 3 ? 0 : st + 1;
    }

    // Epilogue: +bias, literal jax MX e5m2 quant-dequant over 32 consecutive n.
#pragma unroll
    for (int mf = 0; mf < 2; mf++) {
#pragma unroll
        for (int h = 0; h < 2; h++) {
            int rl = wm * 32 + mf * 16 + h * 8 + gid;
            float v[8];
            float amax = 0.f;
#pragma unroll
            for (int nf = 0; nf < 4; nf++) {
                float2 p = upk2(acc2[mf][nf][h]);
                float v0 = p.x + sBias[wn * 32 + nf * 8 + tig * 2];
                float v1 = p.y + sBias[wn * 32 + nf * 8 + tig * 2 + 1];
                v[nf * 2 + 0] = v0;
                v[nf * 2 + 1] = v1;
                amax = fmaxf(amax, fmaxf(fabsf(v0), fabsf(v1)));
            }
            amax = fmaxf(amax, __shfl_xor_sync(0xffffffffu, amax, 1));
            amax = fmaxf(amax, __shfl_xor_sync(0xffffffffu, amax, 2));
            float scale = jax_scale(amax);
            float* orow = out + (size_t)(m0 + rl) * N_DIM + n0 + wn * 32;
#pragma unroll
            for (int nf = 0; nf < 4; nf++) {
                float2 qv;
#pragma unroll
                for (int j = 0; j < 2; j++) {
                    float t = v[nf * 2 + j] / scale;
                    float av = fabsf(t);
                    float r = 0.f;
                    if (av > 0.f) {
                        float sat = fminf(av, 57344.f);
                        int e = jax_floor_log2(sat);
                        e = e < -14 ? -14 : e;
                        float step = sStep[e + 14];
                        float q = rintf(sat / step) * step;   // literal ref math
                        r = copysignf(q, t) * scale;
                    }
                    (j == 0 ? qv.x : qv.y) = r;
                }
                *reinterpret_cast<float2*>(orow + nf * 8 + tig * 2) = qv;
            }
        }
    }
}

extern "C" void kernel_launch(void* const* d_in, const int* in_sizes, int n_in,
                              void* d_out, int out_size) {
    const float* x = (const float*)d_in[0];
    const float* w = (const float*)d_in[1];
    const float* bias = (const float*)d_in[2];
    float* out = (float*)d_out;

    int Mtot = in_sizes[0] / K_DIM;   // 65536
    int nbx = in_sizes[0] / 32;
    int nbw = in_sizes[1] / 32;

    void *pxv = nullptr, *pwv = nullptr, *pxs = nullptr, *pws = nullptr;
    cudaGetSymbolAddress(&pxv, g_xv);
    cudaGetSymbolAddress(&pwv, g_wv);
    cudaGetSymbolAddress(&pxs, g_xs);
    cudaGetSymbolAddress(&pws, g_ws);

    quant_v<<<(nbx + 255) / 256, 256>>>(x, (__nv_bfloat16*)pxv, (float*)pxs, nbx, Mtot);
    quant_v<<<(nbw + 255) / 256, 256>>>(w, (__nv_bfloat16*)pwv, (float*)pws, nbw, N_DIM);

    const int dyn_smem = 3 * STG_ELEMS * 2 * 2;   // 61440 bytes
    cudaFuncSetAttribute(gemm_qd, cudaFuncAttributeMaxDynamicSharedMemorySize, dyn_smem);
    dim3 grid(N_DIM / BN, Mtot / BM);
    gemm_qd<<<grid, 512, dyn_smem>>>(bias, out, Mtot);
}

// round 9
// speedup vs baseline: 2.7360x; 1.0366x over previous
#include <cuda_runtime.h>
#include <cuda_fp8.h>
#include <cstdint>
#include <cstddef>

#define K_DIM 1024
#define N_DIM 1024
#define NKB 32
#define LN2F 0.69314718246459960938f

#define BM 128
#define BN 128
#define BK 32                 // bytes per k-block (fp8) == one MX block
#define RSTRIDE 48            // bytes per smem row (32 data + 16 pad)
#define STG_BYTES (BM * RSTRIDE)

// Exact e5m2 grid values stored AS fp8 + per-32-block scales (fp32, inexact jax)
__device__ __align__(16) uint8_t g_xv[(size_t)8 * 8192 * 1024];
__device__ __align__(16) uint8_t g_wv[(size_t)1024 * 1024];
__device__ __align__(16) float g_xs[(size_t)NKB * 65536];   // [kb][row]
__device__ __align__(16) float g_ws[(size_t)NKB * 1024];    // [kb][row]

// floor(logf(s)/ln2f) with exponent-bits fast path (bitwise-equal in fast region)
__device__ __forceinline__ int jax_floor_log2(float s) {
    uint32_t b = __float_as_uint(s);
    uint32_t mant = b & 0x7fffffu;
    int ef = (int)(b >> 23);
    if (ef == 0 || mant >= 0x7ff000u || (mant != 0u && mant <= 0x4000u))
        return (int)floorf(logf(s) / LN2F);
    return ef - 127;
}

// Literal jax block scale: expf((floor(log2(amax)) - 15) * ln2f)
__device__ __forceinline__ float jax_scale(float amax) {
    if (!(amax > 0.f)) return 1.f;
    int E = jax_floor_log2(amax);
    return expf((float)(E - 15) * LN2F);
}

// One thread = one 32-element MX block. Emits exact e5m2 grid values (fp8) + scale.
__global__ void quant_v(const float* __restrict__ x, uint8_t* __restrict__ qv,
                        float* __restrict__ qs, int nblk, int rows) {
    __shared__ float sStep[30];
    if (threadIdx.x < 30) sStep[threadIdx.x] = expf((float)((int)threadIdx.x - 16) * LN2F);
    __syncthreads();
    int b = blockIdx.x * blockDim.x + threadIdx.x;
    if (b >= nblk) return;
    const float4* p = reinterpret_cast<const float4*>(x) + (size_t)b * 8;
    float4 v[8];
    float amax = 0.f;
#pragma unroll
    for (int i = 0; i < 8; i++) {
        v[i] = p[i];
        amax = fmaxf(amax, fmaxf(fmaxf(fabsf(v[i].x), fabsf(v[i].y)),
                                 fmaxf(fabsf(v[i].z), fabsf(v[i].w))));
    }
    float scale = jax_scale(amax);
    const float* f = reinterpret_cast<const float*>(v);
    uint4 ov[2];                                   // 32 fp8 bytes
    uint8_t* o = reinterpret_cast<uint8_t*>(ov);
#pragma unroll
    for (int i = 0; i < 32; i++) {
        float t = f[i] / scale;            // true div: selection bitwise as ref
        float av = fabsf(t);
        float r = 0.f;
        if (av > 0.f) {
            float sat = fminf(av, 57344.f);
            int e = jax_floor_log2(sat);
            e = e < -14 ? -14 : e;
            float step = sStep[e + 14];    // bitwise == expf((e-2)*ln2f)
            float n = rintf(sat / step);   // true div: bitwise as ref
            r = copysignf(ldexpf(n, e - 2), t);   // EXACT e5m2 grid value
        }
        o[i] = __nv_cvt_float_to_fp8(r, __NV_SATFINITE, __NV_E5M2);  // exact
    }
    uint4* dst = reinterpret_cast<uint4*>(qv) + (size_t)b * 2;
    dst[0] = ov[0];
    dst[1] = ov[1];
    qs[(size_t)(b & 31) * rows + (b >> 5)] = scale;
}

__device__ __forceinline__ void cp_async16(uint32_t dst, const void* src) {
    asm volatile("cp.async.cg.shared.global [%0], [%1], 16;\n" :: "r"(dst), "l"(src));
}

__device__ __forceinline__ unsigned long long pk2(float lo, float hi) {
    unsigned long long r;
    asm("mov.b64 %0, {%1, %2};" : "=l"(r) : "f"(lo), "f"(hi));
    return r;
}
__device__ __forceinline__ float2 upk2(unsigned long long v) {
    float2 r;
    asm("mov.b64 {%0, %1}, %2;" : "=f"(r.x), "=f"(r.y) : "l"(v));
    return r;
}
__device__ __forceinline__ unsigned long long mul2(unsigned long long a,
                                                   unsigned long long b) {
    unsigned long long r;
    asm("mul.rn.f32x2 %0, %1, %2;" : "=l"(r) : "l"(a), "l"(b));
    return r;
}
__device__ __forceinline__ void fma2(unsigned long long& acc, unsigned long long a,
                                     unsigned long long b) {
    asm("fma.rn.f32x2 %0, %1, %2, %0;" : "+l"(acc) : "l"(a), "l"(b));
}

// 128x128 tile GEMM, 16 warps (warp tile 32x32), 3-stage cp.async pipeline,
// fp8-e5m2 m16n8k32 MMA (one per MX block) + packed-f32x2 scale fold;
// literal jax out-quant in epilogue.
__global__ __launch_bounds__(512) void gemm_qd(const float* __restrict__ bias,
                                               float* __restrict__ out, int mrows) {
    __shared__ uint8_t sA[3][STG_BYTES];
    __shared__ uint8_t sB[3][STG_BYTES];
    __shared__ float sSX[3][BM];
    __shared__ float sSW[3][BN];
    __shared__ float sBias[BN];
    __shared__ float sStep[30];

    const int tid = threadIdx.x;
    const int m0 = blockIdx.y * BM;
    const int n0 = blockIdx.x * BN;
    if (tid < 30) sStep[tid] = expf((float)(tid - 16) * LN2F);
    if (tid < BN) sBias[tid] = bias[n0 + tid];

    const int lane = tid & 31;
    const int warp = tid >> 5;          // 0..15
    const int wm = warp >> 2;           // 0..3  (32 rows)
    const int wn = warp & 3;            // 0..3  (32 cols = one quant block)

    uint32_t sAu[3], sBu[3], sSXu[3], sSWu[3];
#pragma unroll
    for (int s = 0; s < 3; s++) {
        sAu[s] = (uint32_t)__cvta_generic_to_shared(&sA[s][0]);
        sBu[s] = (uint32_t)__cvta_generic_to_shared(&sB[s][0]);
        sSXu[s] = (uint32_t)__cvta_generic_to_shared(&sSX[s][0]);
        sSWu[s] = (uint32_t)__cvta_generic_to_shared(&sSW[s][0]);
    }

    unsigned long long acc2[2][4][2];
#pragma unroll
    for (int i = 0; i < 2; i++)
#pragma unroll
        for (int j = 0; j < 4; j++)
#pragma unroll
            for (int h = 0; h < 2; h++) acc2[i][j][h] = 0ull;

    // 512 threads: tid<256 loads one 16B chunk of A, tid>=256 one of B.
    const int lrow = (tid & 255) >> 1, lch = tid & 1;
    auto load_stage = [&](int stage, int kt) {
        int k0 = kt * BK;
        if (tid < 256)
            cp_async16(sAu[stage] + (uint32_t)(lrow * RSTRIDE + lch * 16),
                       &g_xv[(size_t)(m0 + lrow) * K_DIM + k0 + lch * 16]);
        else
            cp_async16(sBu[stage] + (uint32_t)(lrow * RSTRIDE + lch * 16),
                       &g_wv[(size_t)(n0 + lrow) * K_DIM + k0 + lch * 16]);
        if (tid < 32)
            cp_async16(sSXu[stage] + tid * 16, &g_xs[(size_t)kt * mrows + m0 + tid * 4]);
        else if (tid < 64)
            cp_async16(sSWu[stage] + (tid - 32) * 16,
                       &g_ws[(size_t)kt * N_DIM + n0 + (tid - 32) * 4]);
        asm volatile("cp.async.commit_group;\n");
    };

    const int gid = lane >> 2, tig = lane & 3;
    const int NK = K_DIM / BK;   // 32

    load_stage(0, 0);
    load_stage(1, 1);

    int st = 0;
    for (int kt = 0; kt < NK; kt++) {
        if (kt < NK - 1) {
            asm volatile("cp.async.wait_group 1;\n");
        } else {
            asm volatile("cp.async.wait_group 0;\n");
        }
        __syncthreads();
        if (kt + 2 < NK) {
            int pf = st + 2 >= 3 ? st - 1 : st + 2;
            load_stage(pf, kt + 2);
        }

        // A fragments: one x4 per m16 tile covers full k32 (32 bytes/row).
        uint32_t a[2][4];
#pragma unroll
        for (int mf = 0; mf < 2; mf++) {
            uint32_t addr = sAu[st] +
                (uint32_t)((wm * 32 + mf * 16 + (lane & 15)) * RSTRIDE +
                           (lane >> 4) * 16);
            asm volatile("ldmatrix.sync.aligned.m8n8.x4.shared.b16 {%0,%1,%2,%3}, [%4];\n"
                         : "=r"(a[mf][0]), "=r"(a[mf][1]), "=r"(a[mf][2]), "=r"(a[mf][3])
                         : "r"(addr));
        }
        // B fragments: one x4 per PAIR of n8 tiles.
        uint32_t b[4][2];
#pragma unroll
        for (int np = 0; np < 2; np++) {
            uint32_t addr = sBu[st] +
                (uint32_t)((wn * 32 + np * 16 + ((lane >> 4) & 1) * 8 + (lane & 7)) * RSTRIDE +
                           ((lane >> 3) & 1) * 16);
            asm volatile("ldmatrix.sync.aligned.m8n8.x4.shared.b16 {%0,%1,%2,%3}, [%4];\n"
                         : "=r"(b[np * 2][0]), "=r"(b[np * 2][1]),
                           "=r"(b[np * 2 + 1][0]), "=r"(b[np * 2 + 1][1])
                         : "r"(addr));
        }

        float c[2][4][4];
#pragma unroll
        for (int mf = 0; mf < 2; mf++)
#pragma unroll
            for (int nf = 0; nf < 4; nf++) {
                c[mf][nf][0] = 0.f; c[mf][nf][1] = 0.f;
                c[mf][nf][2] = 0.f; c[mf][nf][3] = 0.f;
                asm volatile(
                    "mma.sync.aligned.m16n8k32.row.col.f32.e5m2.e5m2.f32 "
                    "{%0,%1,%2,%3}, {%4,%5,%6,%7}, {%8,%9}, {%0,%1,%2,%3};\n"
                    : "+f"(c[mf][nf][0]), "+f"(c[mf][nf][1]),
                      "+f"(c[mf][nf][2]), "+f"(c[mf][nf][3])
                    : "r"(a[mf][0]), "r"(a[mf][1]), "r"(a[mf][2]), "r"(a[mf][3]),
                      "r"(b[nf][0]), "r"(b[nf][1]));
            }

        // Packed scale fold: acc += c * (sx * sw), element-wise RN.
        unsigned long long sxp[2][2], swp[4];
#pragma unroll
        for (int mf = 0; mf < 2; mf++) {
            float s0 = sSX[st][wm * 32 + mf * 16 + gid];
            float s1 = sSX[st][wm * 32 + mf * 16 + 8 + gid];
            sxp[mf][0] = pk2(s0, s0);
            sxp[mf][1] = pk2(s1, s1);
        }
#pragma unroll
        for (int nf = 0; nf < 4; nf++)
            swp[nf] = pk2(sSW[st][wn * 32 + nf * 8 + tig * 2],
                          sSW[st][wn * 32 + nf * 8 + tig * 2 + 1]);
#pragma unroll
        for (int mf = 0; mf < 2; mf++)
#pragma unroll
            for (int nf = 0; nf < 4; nf++) {
                fma2(acc2[mf][nf][0], pk2(c[mf][nf][0], c[mf][nf][1]),
                     mul2(sxp[mf][0], swp[nf]));
                fma2(acc2[mf][nf][1], pk2(c[mf][nf][2], c[mf][nf][3]),
                     mul2(sxp[mf][1], swp[nf]));
            }

        st = st + 1 >= 3 ? 0 : st + 1;
    }

    // Epilogue: +bias, literal jax MX e5m2 quant-dequant over 32 consecutive n.
#pragma unroll
    for (int mf = 0; mf < 2; mf++) {
#pragma unroll
        for (int h = 0; h < 2; h++) {
            int rl = wm * 32 + mf * 16 + h * 8 + gid;
            float v[8];
            float amax = 0.f;
#pragma unroll
            for (int nf = 0; nf < 4; nf++) {
                float2 p = upk2(acc2[mf][nf][h]);
                float v0 = p.x + sBias[wn * 32 + nf * 8 + tig * 2];
                float v1 = p.y + sBias[wn * 32 + nf * 8 + tig * 2 + 1];
                v[nf * 2 + 0] = v0;
                v[nf * 2 + 1] = v1;
                amax = fmaxf(amax, fmaxf(fabsf(v0), fabsf(v1)));
            }
            amax = fmaxf(amax, __shfl_xor_sync(0xffffffffu, amax, 1));
            amax = fmaxf(amax, __shfl_xor_sync(0xffffffffu, amax, 2));
            float scale = jax_scale(amax);
            float* orow = out + (size_t)(m0 + rl) * N_DIM + n0 + wn * 32;
#pragma unroll
            for (int nf = 0; nf < 4; nf++) {
                float2 qv;
#pragma unroll
                for (int j = 0; j < 2; j++) {
                    float t = v[nf * 2 + j] / scale;
                    float av = fabsf(t);
                    float r = 0.f;
                    if (av > 0.f) {
                        float sat = fminf(av, 57344.f);
                        int e = jax_floor_log2(sat);
                        e = e < -14 ? -14 : e;
                        float step = sStep[e + 14];
                        float q = rintf(sat / step) * step;   // literal ref math
                        r = copysignf(q, t) * scale;
                    }
                    (j == 0 ? qv.x : qv.y) = r;
                }
                *reinterpret_cast<float2*>(orow + nf * 8 + tig * 2) = qv;
            }
        }
    }
}

extern "C" void kernel_launch(void* const* d_in, const int* in_sizes, int n_in,
                              void* d_out, int out_size) {
    const float* x = (const float*)d_in[0];
    const float* w = (const float*)d_in[1];
    const float* bias = (const float*)d_in[2];
    float* out = (float*)d_out;

    int Mtot = in_sizes[0] / K_DIM;   // 65536
    int nbx = in_sizes[0] / 32;
    int nbw = in_sizes[1] / 32;

    void *pxv = nullptr, *pwv = nullptr, *pxs = nullptr, *pws = nullptr;
    cudaGetSymbolAddress(&pxv, g_xv);
    cudaGetSymbolAddress(&pwv, g_wv);
    cudaGetSymbolAddress(&pxs, g_xs);
    cudaGetSymbolAddress(&pws, g_ws);

    quant_v<<<(nbx + 255) / 256, 256>>>(x, (uint8_t*)pxv, (float*)pxs, nbx, Mtot);
    quant_v<<<(nbw + 255) / 256, 256>>>(w, (uint8_t*)pwv, (float*)pws, nbw, N_DIM);

    dim3 grid(N_DIM / BN, Mtot / BM);
    gemm_qd<<<grid, 512>>>(bias, out, Mtot);
}